// round 8
// baseline (speedup 1.0000x reference)
#include <cuda_runtime.h>
#include <cstdint>

// Embedder via two-table gather.
// input_ids are integers in [0, VOCAB), so the scalar MLP
// out = w2 @ relu(x*w1+b1) + b2 is a pure function of a 15-bit int.
// Prepass materializes mlp_table[VOCAB][64]; main kernel is a branchless
// gather from (mask ? emb_table : mlp_table). Gather is L2-capped
// (~268MB through LTS), so the layout aims for minimal instructions and
// exactly one 32-position chunk per warp.

#define VOCAB 32000
#define EMBED_DIM 64

__device__ float g_mlp_table[VOCAB * EMBED_DIM];   // 8.2 MB static scratch

// ---------------- prepass: build MLP table ----------------
// w2/w1/b1/b2 all end up in registers; row loop is pure FFMA + 256B store.
__global__ __launch_bounds__(256) void mlp_table_kernel(
    const float* __restrict__ w1,
    const float* __restrict__ b1,
    const float* __restrict__ w2,
    const float* __restrict__ b2)
{
    __shared__ float2 s_w1b1[16];
    __shared__ float2 s_w2t[16][32];   // [j][lane] = {w2[2L][j], w2[2L+1][j]}
    __shared__ float2 s_b2[32];

    if (threadIdx.x < 16)
        s_w1b1[threadIdx.x] = make_float2(w1[threadIdx.x], b1[threadIdx.x]);
    if (threadIdx.x < 32)
        s_b2[threadIdx.x] = make_float2(b2[2 * threadIdx.x], b2[2 * threadIdx.x + 1]);
    // coalesced read of w2 (1024 floats), transposed scatter into shared
    for (int idx = threadIdx.x; idx < 1024; idx += blockDim.x) {
        const int row = idx >> 4;
        const int j   = idx & 15;
        const float v = w2[idx];
        if (row & 1) s_w2t[j][row >> 1].y = v;
        else         s_w2t[j][row >> 1].x = v;
    }
    __syncthreads();

    const int lane  = threadIdx.x & 31;
    const int warp  = (int)((blockIdx.x * blockDim.x + threadIdx.x) >> 5);
    const int nwarp = (int)((gridDim.x * blockDim.x) >> 5);

    float w2a[16], w2b[16], w1r[16], b1r[16];
#pragma unroll
    for (int j = 0; j < 16; ++j) {
        const float2 t = s_w2t[j][lane];
        w2a[j] = t.x; w2b[j] = t.y;
        const float2 wb = s_w1b1[j];
        w1r[j] = wb.x; b1r[j] = wb.y;
    }
    const float2 bb = s_b2[lane];
    float2* tab2 = reinterpret_cast<float2*>(g_mlp_table);

    for (int v = warp; v < VOCAB; v += nwarp) {
        const float x = (float)v;
        float acc0 = bb.x, acc1 = bb.y;
#pragma unroll
        for (int j = 0; j < 16; ++j) {
            const float h = fmaxf(fmaf(x, w1r[j], b1r[j]), 0.0f);
            acc0 = fmaf(w2a[j], h, acc0);
            acc1 = fmaf(w2b[j], h, acc1);
        }
        tab2[(size_t)v * 32 + lane] = make_float2(acc0, acc1);
    }
}

// ---------------- main: branchless dual-table gather ----------------
// Exactly one 32-position chunk per warp (grid sized to nchunk).
// 16 lanes per position (float4), 2 positions per warp instruction,
// 8 gathers in flight per unroll group, streaming stores.
__global__ __launch_bounds__(256) void gather_kernel(
    const float* __restrict__ input_ids,
    const int*   __restrict__ type_mask,
    const float* __restrict__ emb_table,
    float*       __restrict__ out,
    int n_pos)
{
    const int lane = threadIdx.x & 31;
    const int half = lane >> 4;
    const int sub  = lane & 15;
    const int c    = (int)((blockIdx.x * blockDim.x + threadIdx.x) >> 5);

    const int base  = c << 5;
    if (base >= n_pos) return;
    const int pos_l = base + lane;

    int pk = 0;
    if (pos_l < n_pos) {
        const int id = (int)__ldg(&input_ids[pos_l]);
        const int m  = __ldg(&type_mask[pos_l]);
        pk = id | (m << 16);
    }
    const int pmax = (n_pos - base < 32) ? (n_pos - base) : 32;

    const float* mlp_table = g_mlp_table;
    float4* out4 = reinterpret_cast<float4*>(out);

#pragma unroll
    for (int p = 0; p < 32; p += 16) {           // 8 pairs per group
        int pks[8]; float4 r[8];
#pragma unroll
        for (int q = 0; q < 8; ++q)
            pks[q] = __shfl_sync(0xffffffffu, pk, p + 2 * q + half);
#pragma unroll
        for (int q = 0; q < 8; ++q) {
            const int id = pks[q] & 0xFFFF;
            const float* t = (pks[q] >> 16) ? emb_table : mlp_table;
            r[q] = __ldg(reinterpret_cast<const float4*>(t + (size_t)id * 64) + sub);
        }
        if (p + 16 <= pmax) {
#pragma unroll
            for (int q = 0; q < 8; ++q)
                __stcs(&out4[(size_t)(base + p + 2 * q + half) * 16 + sub], r[q]);
        } else {
#pragma unroll
            for (int q = 0; q < 8; ++q) {
                const int pp = p + 2 * q + half;
                if (pp < pmax)
                    __stcs(&out4[(size_t)(base + pp) * 16 + sub], r[q]);
            }
        }
    }
}

extern "C" void kernel_launch(void* const* d_in, const int* in_sizes, int n_in,
                              void* d_out, int out_size)
{
    const float* input_ids = (const float*)d_in[0];
    const int*   type_mask = (const int*)  d_in[1];
    const float* emb_table = (const float*)d_in[2];
    const float* w1        = (const float*)d_in[3];
    const float* b1        = (const float*)d_in[4];
    const float* w2        = (const float*)d_in[5];
    const float* b2        = (const float*)d_in[6];
    float*       out       = (float*)d_out;

    const int n_pos = in_sizes[0];  // B*S = 524288

    // Prepass: 16384 warps, ~2 rows each, register-resident weights
    mlp_table_kernel<<<2048, 256>>>(w1, b1, w2, b2);

    // Gather: one 32-position chunk per warp, grid exactly covers n_pos
    const int nchunk = (n_pos + 31) >> 5;
    const int blocks = (nchunk + 7) >> 3;     // 8 warps per block
    gather_kernel<<<blocks, 256>>>(input_ids, type_mask, emb_table, out, n_pos);
}

// round 9
// speedup vs baseline: 1.1992x; 1.1992x over previous
#include <cuda_runtime.h>
#include <cstdint>

// Embedder. out(x) = w2 @ relu(w1*x+b1) + b2 is PIECEWISE LINEAR in the
// scalar x with <=16 kinks at t_j = -b1_j/w1_j. Prepass builds a 17-segment
// table A[seg][64], B[seg][64] (8.7KB, L1-resident everywhere) + thresholds.
// Main kernel: token positions gather emb_table rows; numeric positions
// compute seg = sum(x > t_j) and evaluate A*x+B. No 8MB MLP table, no
// numeric L2 gather traffic.

#define VOCAB 32000
#define EMBED_DIM 64
#define NSEG 17

__device__ float g_segA[NSEG * EMBED_DIM];
__device__ float g_segB[NSEG * EMBED_DIM];
__device__ float g_thresh[16];

// ---------------- prepass: 17 blocks x 64 threads ----------------
__global__ void seg_table_kernel(
    const float* __restrict__ w1,
    const float* __restrict__ b1,
    const float* __restrict__ w2,
    const float* __restrict__ b2)
{
    const int seg = blockIdx.x;     // 0..16
    const int d   = threadIdx.x;    // 0..63

    float w1v[16], b1v[16], t[16];
    bool  pos[16];
#pragma unroll
    for (int j = 0; j < 16; ++j) {
        w1v[j] = __ldg(&w1[j]);
        b1v[j] = __ldg(&b1[j]);
        if (w1v[j] > 0.0f)      { t[j] = -b1v[j] / w1v[j]; pos[j] = true;  }
        else if (w1v[j] < 0.0f) { t[j] = -b1v[j] / w1v[j]; pos[j] = false; }
        else { pos[j] = true; t[j] = (b1v[j] > 0.0f) ? -1e30f : 1e30f; }
    }
    // rank_j = #thresholds strictly before t_j (ties broken by index)
    int rank[16];
#pragma unroll
    for (int j = 0; j < 16; ++j) {
        int r = 0;
#pragma unroll
        for (int k = 0; k < 16; ++k)
            r += (t[k] < t[j]) || (t[k] == t[j] && k < j);
        rank[j] = r;
    }
    // seg = count of (x > t_k); unit j sees x > t_j  <=>  seg > rank_j
    float A = 0.0f, B = __ldg(&b2[d]);
#pragma unroll
    for (int j = 0; j < 16; ++j) {
        const bool gt = (seg > rank[j]);                 // x > t_j on this seg
        const bool active = pos[j] ? gt : !gt;           // relu input > 0
        if (active) {
            const float w = __ldg(&w2[d * 16 + j]);
            A = fmaf(w, w1v[j], A);
            B = fmaf(w, b1v[j], B);
        }
    }
    g_segA[seg * EMBED_DIM + d] = A;
    g_segB[seg * EMBED_DIM + d] = B;
    if (seg == 0 && d < 16) g_thresh[d] = t[d];
}

// ---------------- main: gather / piecewise-linear eval ----------------
// One 32-position chunk per warp. 16 lanes per position (float4), 2 positions
// per warp instruction, 8 first-loads in flight, streaming stores.
__global__ __launch_bounds__(256) void gather_kernel(
    const float* __restrict__ input_ids,
    const int*   __restrict__ type_mask,
    const float* __restrict__ emb_table,
    float*       __restrict__ out,
    int n_pos)
{
    const int lane = threadIdx.x & 31;
    const int half = lane >> 4;
    const int sub  = lane & 15;
    const int c    = (int)((blockIdx.x * blockDim.x + threadIdx.x) >> 5);

    const int base = c << 5;
    if (base >= n_pos) return;
    const int pos_l = base + lane;

    // pk layout: [16:0]=id, [16]=mask, [21:17]=seg
    int pk = 0;
    if (pos_l < n_pos) {
        const int id = (int)__ldg(&input_ids[pos_l]);
        const int m  = __ldg(&type_mask[pos_l]);
        int seg = 0;
        if (!m) {
            const float x = (float)id;
#pragma unroll
            for (int j = 0; j < 16; ++j)
                seg += (x > __ldg(&g_thresh[j]));
        }
        pk = id | (m << 16) | (seg << 17);
    }
    const int pmax = (n_pos - base < 32) ? (n_pos - base) : 32;

    const float4* segA4 = reinterpret_cast<const float4*>(g_segA);
    const float4* segB4 = reinterpret_cast<const float4*>(g_segB);
    float4* out4 = reinterpret_cast<float4*>(out);

#pragma unroll
    for (int p = 0; p < 32; p += 16) {           // 8 pairs per group
        int pks[8]; float4 r[8];
#pragma unroll
        for (int q = 0; q < 8; ++q)
            pks[q] = __shfl_sync(0xffffffffu, pk, p + 2 * q + half);
        // first loads, branchless address select, 8 in flight:
        // token -> emb row;  numeric -> A row (L1-resident 8.7KB table)
#pragma unroll
        for (int q = 0; q < 8; ++q) {
            const int id  = pks[q] & 0xFFFF;
            const int sg  = pks[q] >> 17;
            const float4* p1 = (pks[q] & 0x10000)
                ? reinterpret_cast<const float4*>(emb_table + (size_t)id * 64) + sub
                : segA4 + sg * 16 + sub;
            r[q] = __ldg(p1);
        }
        // numeric finish: B row (L1 hit) + fma
#pragma unroll
        for (int q = 0; q < 8; ++q) {
            if (!(pks[q] & 0x10000)) {
                const int sg = pks[q] >> 17;
                const float x = (float)(pks[q] & 0xFFFF);
                const float4 B = __ldg(segB4 + sg * 16 + sub);
                r[q].x = fmaf(r[q].x, x, B.x);
                r[q].y = fmaf(r[q].y, x, B.y);
                r[q].z = fmaf(r[q].z, x, B.z);
                r[q].w = fmaf(r[q].w, x, B.w);
            }
        }
        if (p + 16 <= pmax) {
#pragma unroll
            for (int q = 0; q < 8; ++q)
                __stcs(&out4[(size_t)(base + p + 2 * q + half) * 16 + sub], r[q]);
        } else {
#pragma unroll
            for (int q = 0; q < 8; ++q) {
                const int pp = p + 2 * q + half;
                if (pp < pmax)
                    __stcs(&out4[(size_t)(base + pp) * 16 + sub], r[q]);
            }
        }
    }
}

extern "C" void kernel_launch(void* const* d_in, const int* in_sizes, int n_in,
                              void* d_out, int out_size)
{
    const float* input_ids = (const float*)d_in[0];
    const int*   type_mask = (const int*)  d_in[1];
    const float* emb_table = (const float*)d_in[2];
    const float* w1        = (const float*)d_in[3];
    const float* b1        = (const float*)d_in[4];
    const float* w2        = (const float*)d_in[5];
    const float* b2        = (const float*)d_in[6];
    float*       out       = (float*)d_out;

    const int n_pos = in_sizes[0];  // B*S = 524288

    // Tiny prepass: 17x64 piecewise-linear segment table (4.4KB writes)
    seg_table_kernel<<<NSEG, EMBED_DIM>>>(w1, b1, w2, b2);

    // Main: one 32-position chunk per warp
    const int nchunk = (n_pos + 31) >> 5;
    const int blocks = (nchunk + 7) >> 3;     // 8 warps per block
    gather_kernel<<<blocks, 256>>>(input_ids, type_mask, emb_table, out, n_pos);
}